// round 3
// baseline (speedup 1.0000x reference)
#include <cuda_runtime.h>

// KDE: density[n] = (1/M) * sum_m exp( -0.5*||x_n - d_m||^2 / sqrt(2*pi) )
// with ||x-d||^2 = ||x||^2 + ||d||^2 - 2 x.d  (GEMM trick, matching reference).
//
// KEXP = -(0.5/sqrt(2*pi)) * log2(e)  so that exp(arg) = exp2(KEXP * sq)

#define DD   128   // feature dim (fixed by problem)
#define BN   128   // rows of x per block
#define BM   128   // rows of data per block
#define KC   16    // K-chunk staged through smem
#define PAD  4     // smem row padding (keeps 16B alignment, reduces STS conflicts)
#define NMAX 8192

__device__ float g_xn2[NMAX];
__device__ float g_dn2[NMAX];

__device__ __forceinline__ float fast_ex2(float x) {
    float y;
    asm("ex2.approx.f32 %0, %1;" : "=f"(y) : "f"(x));
    return y;
}

__global__ void norms_kernel(const float* __restrict__ x,
                             const float* __restrict__ data,
                             int N, int M) {
    int i = blockIdx.x * blockDim.x + threadIdx.x;
    if (i < N) {
        const float4* r = reinterpret_cast<const float4*>(x + (size_t)i * DD);
        float s = 0.f;
        #pragma unroll
        for (int j = 0; j < DD / 4; j++) {
            float4 v = r[j];
            s = fmaf(v.x, v.x, s);
            s = fmaf(v.y, v.y, s);
            s = fmaf(v.z, v.z, s);
            s = fmaf(v.w, v.w, s);
        }
        g_xn2[i] = s;
    }
    if (i < M) {
        const float4* r = reinterpret_cast<const float4*>(data + (size_t)i * DD);
        float s = 0.f;
        #pragma unroll
        for (int j = 0; j < DD / 4; j++) {
            float4 v = r[j];
            s = fmaf(v.x, v.x, s);
            s = fmaf(v.y, v.y, s);
            s = fmaf(v.z, v.z, s);
            s = fmaf(v.w, v.w, s);
        }
        g_dn2[i] = s;
    }
}

__global__ __launch_bounds__(256, 2)
void kde_kernel(const float* __restrict__ x,
                const float* __restrict__ data,
                float* __restrict__ out,
                int N, int M) {
    __shared__ float As[KC][BN + PAD];  // [k][n]
    __shared__ float Bs[KC][BM + PAD];  // [k][m]

    const int tid = threadIdx.x;
    const int tx  = tid & 15;   // m direction (8 cols each)
    const int ty  = tid >> 4;   // n direction (8 rows each)
    const int n0  = blockIdx.y * BN;
    const int m0  = blockIdx.x * BM;

    float acc[8][8];
    #pragma unroll
    for (int i = 0; i < 8; i++)
        #pragma unroll
        for (int j = 0; j < 8; j++)
            acc[i][j] = 0.f;

    // Global-load mapping: 256 threads cover a 128-row x 16-col chunk as float4s.
    const int lrow = tid >> 2;   // 0..63 (each thread also does lrow+64)
    const int lc4  = tid & 3;    // which float4 within the 16-wide K chunk

    for (int k0 = 0; k0 < DD; k0 += KC) {
        #pragma unroll
        for (int h = 0; h < 2; h++) {
            const int row = lrow + h * 64;
            float4 va = *reinterpret_cast<const float4*>(
                x + (size_t)(n0 + row) * DD + k0 + lc4 * 4);
            As[lc4 * 4 + 0][row] = va.x;
            As[lc4 * 4 + 1][row] = va.y;
            As[lc4 * 4 + 2][row] = va.z;
            As[lc4 * 4 + 3][row] = va.w;
            float4 vb = *reinterpret_cast<const float4*>(
                data + (size_t)(m0 + row) * DD + k0 + lc4 * 4);
            Bs[lc4 * 4 + 0][row] = vb.x;
            Bs[lc4 * 4 + 1][row] = vb.y;
            Bs[lc4 * 4 + 2][row] = vb.z;
            Bs[lc4 * 4 + 3][row] = vb.w;
        }
        __syncthreads();

        #pragma unroll
        for (int k = 0; k < KC; k++) {
            float a[8], b[8];
            *reinterpret_cast<float4*>(&a[0]) =
                *reinterpret_cast<const float4*>(&As[k][ty * 8]);
            *reinterpret_cast<float4*>(&a[4]) =
                *reinterpret_cast<const float4*>(&As[k][ty * 8 + 4]);
            *reinterpret_cast<float4*>(&b[0]) =
                *reinterpret_cast<const float4*>(&Bs[k][tx * 8]);
            *reinterpret_cast<float4*>(&b[4]) =
                *reinterpret_cast<const float4*>(&Bs[k][tx * 8 + 4]);
            #pragma unroll
            for (int i = 0; i < 8; i++)
                #pragma unroll
                for (int j = 0; j < 8; j++)
                    acc[i][j] = fmaf(a[i], b[j], acc[i][j]);
        }
        __syncthreads();
    }

    // Epilogue: val = exp2( KEXP * (||x||^2 + ||d||^2) + (-2*KEXP) * dot )
    const float KEXP = -0.28777602743432504f;  // -(0.5/sqrt(2pi))*log2(e)
    const float K2   =  0.57555205486865008f;  // -2*KEXP

    float cn[8], cm[8];
    #pragma unroll
    for (int i = 0; i < 8; i++) cn[i] = KEXP * g_xn2[n0 + ty * 8 + i];
    #pragma unroll
    for (int j = 0; j < 8; j++) cm[j] = KEXP * g_dn2[m0 + tx * 8 + j];

    float rs[8];
    #pragma unroll
    for (int i = 0; i < 8; i++) {
        float s = 0.f;
        #pragma unroll
        for (int j = 0; j < 8; j++) {
            float arg = fmaf(acc[i][j], K2, cn[i] + cm[j]);
            s += fast_ex2(arg);
        }
        rs[i] = s;
    }

    // Reduce over tx (16 threads = lane bits [3:0] within each half-warp).
    #pragma unroll
    for (int off = 8; off > 0; off >>= 1)
        #pragma unroll
        for (int i = 0; i < 8; i++)
            rs[i] += __shfl_xor_sync(0xffffffffu, rs[i], off);

    if (tx == 0) {
        const float invM = 1.0f / (float)M;
        #pragma unroll
        for (int i = 0; i < 8; i++)
            atomicAdd(&out[n0 + ty * 8 + i], rs[i] * invM);
    }
}

extern "C" void kernel_launch(void* const* d_in, const int* in_sizes, int n_in,
                              void* d_out, int out_size) {
    const float* x    = (const float*)d_in[0];
    const float* data = (const float*)d_in[1];
    float* out = (float*)d_out;

    const int N = in_sizes[0] / DD;
    const int M = in_sizes[1] / DD;

    // out is poisoned; zero it (memset nodes are graph-capturable).
    cudaMemsetAsync(d_out, 0, (size_t)out_size * sizeof(float));

    const int nmax = (N > M) ? N : M;
    norms_kernel<<<(nmax + 255) / 256, 256>>>(x, data, N, M);

    dim3 grid(M / BM, N / BN);
    kde_kernel<<<grid, 256>>>(x, data, out, N, M);
}